// round 1
// baseline (speedup 1.0000x reference)
#include <cuda_runtime.h>
#include <math.h>

#define NH 8
#define NT 2048
#define NE 512
#define NHT (NH * NT)

// ---------------- scratch (device globals; no allocation allowed) ----------------
__device__ float g_q[NH * NT * NE];        // 33.5 MB
__device__ float g_k[NH * NT * NE];        // 33.5 MB
__device__ float g_v[NH * NT * NE];        // 33.5 MB
__device__ float g_scores[NH * NT * NT];   // 134 MB (softmax in-place)
__device__ float g_heads[NH * NT * NE];    // 33.5 MB  == concat [H*T, E]
__device__ float g_final[NT * NE];         // 4 MB

// ---------------- generic tiled fp32 GEMM ----------------
// C[m,n] = alpha * sum_k A[m,k] * B(k,n)  (+ bias_n[n]) (+ bias_m[m]) (+ addend[m,n])
// TRANS_B = true : B stored [N,K] row-major (B^T applied)  -> C = A * B^T
// TRANS_B = false: B stored [K,N] row-major                -> C = A * B
// Tiles: BM=BN=128, BK=16, 256 threads, 8x8 per-thread microtile.
// Requires M%128==0, N%128==0, K%16==0 (true for all shapes here).
template <bool TRANS_B>
__global__ __launch_bounds__(256)
void gemm_kernel(const float* __restrict__ A, const float* __restrict__ B,
                 float* __restrict__ C,
                 int M, int N, int K,
                 size_t sA, size_t sB, size_t sC,
                 float alpha,
                 const float* __restrict__ bias_n, size_t sBiasN,
                 const float* __restrict__ bias_m,
                 const float* __restrict__ addend)
{
    constexpr int BM = 128, BN = 128, BK = 16, TM = 8, TN = 8;
    __shared__ float As[BK][BM];
    __shared__ float Bs[BK][BN];

    const int bz = blockIdx.z;
    A += (size_t)bz * sA;
    B += (size_t)bz * sB;
    C += (size_t)bz * sC;
    if (bias_n) bias_n += (size_t)bz * sBiasN;

    const int blockRow = blockIdx.y;
    const int blockCol = blockIdx.x;
    const int tid = threadIdx.x;          // 0..255
    const int tr  = tid >> 4;             // 0..15 (row group)
    const int tc  = tid & 15;             // 0..15 (col group)

    float acc[TM][TN];
    #pragma unroll
    for (int i = 0; i < TM; i++)
        #pragma unroll
        for (int j = 0; j < TN; j++) acc[i][j] = 0.0f;

    const float* Atile = A + (size_t)blockRow * BM * K;

    for (int k0 = 0; k0 < K; k0 += BK) {
        // ---- load A tile 128x16, store transposed As[k][m] ----
        {
            const int aRow = tid >> 2;         // 0..63
            const int aCol = (tid & 3) * 4;    // 0,4,8,12
            #pragma unroll
            for (int p = 0; p < 2; p++) {
                const int r = aRow + p * 64;
                float4 v = *reinterpret_cast<const float4*>(
                    Atile + (size_t)r * K + k0 + aCol);
                As[aCol + 0][r] = v.x;
                As[aCol + 1][r] = v.y;
                As[aCol + 2][r] = v.z;
                As[aCol + 3][r] = v.w;
            }
        }
        // ---- load B tile ----
        if (TRANS_B) {
            const float* Btile = B + (size_t)blockCol * BN * K;
            const int bRow = tid >> 2;
            const int bCol = (tid & 3) * 4;
            #pragma unroll
            for (int p = 0; p < 2; p++) {
                const int r = bRow + p * 64;
                float4 v = *reinterpret_cast<const float4*>(
                    Btile + (size_t)r * K + k0 + bCol);
                Bs[bCol + 0][r] = v.x;
                Bs[bCol + 1][r] = v.y;
                Bs[bCol + 2][r] = v.z;
                Bs[bCol + 3][r] = v.w;
            }
        } else {
            const int bRow = tid >> 5;            // 0..7
            const int bCol = (tid & 31) * 4;      // 0..124
            #pragma unroll
            for (int p = 0; p < 2; p++) {
                const int r = bRow + p * 8;
                float4 v = *reinterpret_cast<const float4*>(
                    B + (size_t)(k0 + r) * N + (size_t)blockCol * BN + bCol);
                *reinterpret_cast<float4*>(&Bs[r][bCol]) = v;
            }
        }
        __syncthreads();

        // ---- 8x8 microtile FMAs ----
        #pragma unroll
        for (int kk = 0; kk < BK; kk++) {
            float regM[TM], regN[TN];
            #pragma unroll
            for (int i = 0; i < TM; i++) regM[i] = As[kk][tr * TM + i];
            #pragma unroll
            for (int j = 0; j < TN; j++) regN[j] = Bs[kk][tc * TN + j];
            #pragma unroll
            for (int i = 0; i < TM; i++)
                #pragma unroll
                for (int j = 0; j < TN; j++)
                    acc[i][j] = fmaf(regM[i], regN[j], acc[i][j]);
        }
        __syncthreads();
    }

    // ---- epilogue ----
    #pragma unroll
    for (int i = 0; i < TM; i++) {
        const int m = blockRow * BM + tr * TM + i;
        const float bm = bias_m ? bias_m[m] : 0.0f;
        #pragma unroll
        for (int j = 0; j < TN; j++) {
            const int n = blockCol * BN + tc * TN + j;
            float val = acc[i][j] * alpha;
            if (bias_n) val += bias_n[n];
            val += bm;
            if (addend) val += addend[(size_t)m * N + n];
            C[(size_t)m * N + n] = val;
        }
    }
}

// ---------------- row softmax over g_scores (in-place) ----------------
// rows = NH*NT, cols = NT. 256 threads/row; exp values kept in registers
// (2 global reads + 1 write per element).
__global__ __launch_bounds__(256)
void softmax_kernel(float* __restrict__ S)
{
    const int row = blockIdx.x;
    float* p = S + (size_t)row * NT;
    const int tid = threadIdx.x;
    __shared__ float red[256];

    // pass 1: max
    float mx = -INFINITY;
    #pragma unroll
    for (int i = 0; i < NT / 256; i++) mx = fmaxf(mx, p[tid + i * 256]);
    red[tid] = mx;
    __syncthreads();
    for (int s = 128; s > 0; s >>= 1) {
        if (tid < s) red[tid] = fmaxf(red[tid], red[tid + s]);
        __syncthreads();
    }
    mx = red[0];
    __syncthreads();

    // pass 2: exp into registers, sum
    float e[NT / 256];
    float sum = 0.0f;
    #pragma unroll
    for (int i = 0; i < NT / 256; i++) {
        e[i] = expf(p[tid + i * 256] - mx);
        sum += e[i];
    }
    red[tid] = sum;
    __syncthreads();
    for (int s = 128; s > 0; s >>= 1) {
        if (tid < s) red[tid] += red[tid + s];
        __syncthreads();
    }
    const float inv = 1.0f / red[0];

    // pass 3: write normalized
    #pragma unroll
    for (int i = 0; i < NT / 256; i++) p[tid + i * 256] = e[i] * inv;
}

// ---------------- per-row LayerNorm (population var, eps=1e-4) ----------------
// one block (128 threads) per row of [NT, NE]; each thread holds one float4.
__global__ __launch_bounds__(128)
void layernorm_kernel(const float* __restrict__ X, float* __restrict__ out)
{
    const int row = blockIdx.x;
    const int tid = threadIdx.x;
    const float4 v = reinterpret_cast<const float4*>(X + (size_t)row * NE)[tid];
    __shared__ float red[128];

    red[tid] = v.x + v.y + v.z + v.w;
    __syncthreads();
    for (int s = 64; s > 0; s >>= 1) {
        if (tid < s) red[tid] += red[tid + s];
        __syncthreads();
    }
    const float mean = red[0] * (1.0f / NE);
    __syncthreads();

    const float dx = v.x - mean, dy = v.y - mean, dz = v.z - mean, dw = v.w - mean;
    red[tid] = dx * dx + dy * dy + dz * dz + dw * dw;
    __syncthreads();
    for (int s = 64; s > 0; s >>= 1) {
        if (tid < s) red[tid] += red[tid + s];
        __syncthreads();
    }
    const float rstd = rsqrtf(red[0] * (1.0f / NE) + 1e-4f);

    float4 o;
    o.x = dx * rstd; o.y = dy * rstd; o.z = dz * rstd; o.w = dw * rstd;
    reinterpret_cast<float4*>(out + (size_t)row * NE)[tid] = o;
}

// ---------------- launch ----------------
extern "C" void kernel_launch(void* const* d_in, const int* in_sizes, int n_in,
                              void* d_out, int out_size)
{
    const float* x  = (const float*)d_in[0];
    const float* y  = (const float*)d_in[1];
    const float* z  = (const float*)d_in[2];
    const float* Wq = (const float*)d_in[3];
    const float* bq = (const float*)d_in[4];
    const float* Wk = (const float*)d_in[5];
    const float* bk = (const float*)d_in[6];
    const float* Wv = (const float*)d_in[7];
    const float* bv = (const float*)d_in[8];
    const float* Wf = (const float*)d_in[9];
    const float* bf = (const float*)d_in[10];
    float* out = (float*)d_out;

    float *q, *k, *v, *sc, *hd, *fin;
    cudaGetSymbolAddress((void**)&q,   g_q);
    cudaGetSymbolAddress((void**)&k,   g_k);
    cudaGetSymbolAddress((void**)&v,   g_v);
    cudaGetSymbolAddress((void**)&sc,  g_scores);
    cudaGetSymbolAddress((void**)&hd,  g_heads);
    cudaGetSymbolAddress((void**)&fin, g_final);

    const float inv_sqrt_T = 1.0f / sqrtf((float)NT);

    // 1-3) per-head QKV projections: [T,E] @ W[h]^T + b[h]   (NT layout, batch=H)
    dim3 gQKV(NE / 128, NT / 128, NH);
    gemm_kernel<true><<<gQKV, 256>>>(x, Wq, q, NT, NE, NE,
                                     0, (size_t)NE * NE, (size_t)NT * NE,
                                     1.0f, bq, NE, nullptr, nullptr);
    gemm_kernel<true><<<gQKV, 256>>>(y, Wk, k, NT, NE, NE,
                                     0, (size_t)NE * NE, (size_t)NT * NE,
                                     1.0f, bk, NE, nullptr, nullptr);
    gemm_kernel<true><<<gQKV, 256>>>(z, Wv, v, NT, NE, NE,
                                     0, (size_t)NE * NE, (size_t)NT * NE,
                                     1.0f, bv, NE, nullptr, nullptr);

    // 4) scores = q @ k^T / sqrt(T)   (NT layout, batch=H)
    dim3 gS(NT / 128, NT / 128, NH);
    gemm_kernel<true><<<gS, 256>>>(q, k, sc, NT, NT, NE,
                                   (size_t)NT * NE, (size_t)NT * NE, (size_t)NT * NT,
                                   inv_sqrt_T, nullptr, 0, nullptr, nullptr);

    // 5) row softmax (in-place)
    softmax_kernel<<<NH * NT, 256>>>(sc);

    // 6) heads = att @ v   (NN layout, batch=H)
    dim3 gAV(NE / 128, NT / 128, NH);
    gemm_kernel<false><<<gAV, 256>>>(sc, v, hd, NT, NE, NT,
                                     (size_t)NT * NT, (size_t)NT * NE, (size_t)NT * NE,
                                     1.0f, nullptr, 0, nullptr, nullptr);

    // 7) final[t,e] = sum_j Wf[t,j] * concat[j,e] + bf[t] + z[t,e]
    dim3 gF(NE / 128, NT / 128, 1);
    gemm_kernel<false><<<gF, 256>>>(Wf, hd, fin, NT, NE, NHT,
                                    0, 0, 0,
                                    1.0f, nullptr, 0, bf, z);

    // 8) LayerNorm -> output
    layernorm_kernel<<<NT, 128>>>(fin, out);
}

// round 4
// speedup vs baseline: 2.8241x; 2.8241x over previous
#include <cuda_runtime.h>
#include <cuda_bf16.h>
#include <math.h>
#include <stdint.h>

#define NH 8
#define NT 2048
#define NE 512
#define NHT (NH * NT)
#define SPLITK 8

typedef __nv_bfloat16 bf16;

// ---------------- scratch (device globals; no allocation anywhere) ----------------
// expanded inputs (K-expansion x3 along the contraction dim)
__device__ __align__(256) bf16 g_xe[(size_t)NT * 3 * NE];
__device__ __align__(256) bf16 g_ye[(size_t)NT * 3 * NE];
__device__ __align__(256) bf16 g_ze[(size_t)NT * 3 * NE];
__device__ __align__(256) bf16 g_Wqe[(size_t)NH * NE * 3 * NE];
__device__ __align__(256) bf16 g_Wke[(size_t)NH * NE * 3 * NE];
__device__ __align__(256) bf16 g_Wve[(size_t)NH * NE * 3 * NE];
__device__ __align__(256) bf16 g_Wfe[(size_t)NT * 3 * NHT];
// expanded intermediates
__device__ __align__(256) bf16 g_q[(size_t)NH * NT * 3 * NE];   // A-pattern rows [T,3E]
__device__ __align__(256) bf16 g_k[(size_t)NH * NT * 3 * NE];   // B-pattern rows [T,3E]
__device__ __align__(256) bf16 g_v[(size_t)NH * NE * 3 * NT];   // B-pattern transposed [E,3T]
__device__ __align__(256) float g_sc[(size_t)NH * NT * NT];     // fp32 scores
__device__ __align__(256) bf16 g_att[(size_t)NH * NT * 3 * NT]; // A-pattern [T,3T]
__device__ __align__(256) bf16 g_hd[(size_t)NE * 3 * NHT];      // B-pattern transposed [E,3HT]
__device__ __align__(256) float g_part[(size_t)SPLITK * NT * NE];

// ---------------- small helpers ----------------
__device__ __forceinline__ uint32_t smem_u32(const void* p) {
    uint32_t a;
    asm("{ .reg .u64 t; cvta.to.shared.u64 t, %1; cvt.u32.u64 %0, t; }" : "=r"(a) : "l"(p));
    return a;
}

__device__ __forceinline__ void cp_async16(uint32_t dst, const void* src) {
    asm volatile("cp.async.cg.shared.global [%0], [%1], 16;" :: "r"(dst), "l"(src));
}
#define CP_COMMIT() asm volatile("cp.async.commit_group;")
#define CP_WAIT1()  asm volatile("cp.async.wait_group 1;")

__device__ __forceinline__ void ldm_x4(uint32_t* r, uint32_t addr) {
    asm volatile("ldmatrix.sync.aligned.m8n8.x4.shared.b16 {%0,%1,%2,%3}, [%4];"
                 : "=r"(r[0]), "=r"(r[1]), "=r"(r[2]), "=r"(r[3]) : "r"(addr));
}

__device__ __forceinline__ void mma16816(float* c, const uint32_t* a, const uint32_t* b) {
    asm volatile(
        "mma.sync.aligned.m16n8k16.row.col.f32.bf16.bf16.f32 "
        "{%0,%1,%2,%3}, {%4,%5,%6,%7}, {%8,%9}, {%0,%1,%2,%3};"
        : "+f"(c[0]), "+f"(c[1]), "+f"(c[2]), "+f"(c[3])
        : "r"(a[0]), "r"(a[1]), "r"(a[2]), "r"(a[3]), "r"(b[0]), "r"(b[1]));
}

__device__ __forceinline__ void split_bf(float f, uint32_t& h, uint32_t& l) {
    __nv_bfloat16 hb = __float2bfloat16_rn(f);
    float hf = __bfloat162float(hb);
    __nv_bfloat16 lb = __float2bfloat16_rn(f - hf);
    h = (uint32_t)__bfloat16_as_ushort(hb);
    l = (uint32_t)__bfloat16_as_ushort(lb);
}

// ---------------- input expansion ----------------
// PAT 0 (A role): triple (hi,hi,lo). PAT 1 (B role): triple (hi,lo,hi).
template <int PAT>
__global__ __launch_bounds__(256)
void expand_kernel(const float* __restrict__ src, bf16* __restrict__ dst, long npairs)
{
    long i = (long)blockIdx.x * blockDim.x + threadIdx.x;
    const long stride = (long)gridDim.x * blockDim.x;
    uint32_t* d32 = reinterpret_cast<uint32_t*>(dst);
    for (; i < npairs; i += stride) {
        float2 f = reinterpret_cast<const float2*>(src)[i];
        uint32_t h0, l0, h1, l1;
        split_bf(f.x, h0, l0);
        split_bf(f.y, h1, l1);
        uint32_t w0, w1, w2;
        if (PAT == 0) { w0 = h0 | (h0 << 16); w1 = l0 | (h1 << 16); w2 = h1 | (l1 << 16); }
        else          { w0 = h0 | (l0 << 16); w1 = h0 | (h1 << 16); w2 = l1 | (h1 << 16); }
        d32[3 * i + 0] = w0;
        d32[3 * i + 1] = w1;
        d32[3 * i + 2] = w2;
    }
}

// ---------------- mma.sync GEMM ----------------
// C[M=by*128.., N=bx*128..] = sum_k A[m,k] * B[n,k]   (TN, both row-major, K'-contig)
// EPI 0: fp32 out (alpha)               EPI 1: bf16 expand in-row, A-pattern (+bias_n)
// EPI 2: bf16 expand in-row, B-pattern (+bias_n)
// EPI 3: bf16 expand transposed, B-pattern (+bias_n); col base = z*colPerZ + 3*m
#define BM 128
#define BN 128
#define BKE 64
#define STAGES 3
#define STAGE_BYTES (BM * BKE * 2 + BN * BKE * 2)   // 32768
#define GEMM_SMEM (STAGES * STAGE_BYTES)            // 98304

template <int EPI>
__global__ __launch_bounds__(256, 2)
void mma_gemm(const bf16* __restrict__ A, const bf16* __restrict__ B, void* Cout,
              int Kp, long lda, long ldb, long ldOut,
              long sA, long sB, long sC, long colPerZ,
              float alpha, const float* __restrict__ bias, long sBias)
{
    extern __shared__ char smem[];
    const int tid = threadIdx.x, lane = tid & 31, wid = tid >> 5;
    const int wm = wid & 3, wn = wid >> 2;
    const int m0 = blockIdx.y * BM, n0 = blockIdx.x * BN, z = blockIdx.z;
    A += (long)z * sA;
    B += (long)z * sB;
    if (bias) bias += (long)z * sBias;
    const uint32_t sbase = smem_u32(smem);

    // cooperative load coords: each thread owns 4 16B chunks in one row
    const int ldr  = tid >> 1;          // tile row 0..127
    const int ldc0 = (tid & 1) * 4;     // first chunk 0 or 4
    const bf16* Ag = A + (long)(m0 + ldr) * lda + ldc0 * 8;
    const bf16* Bg = B + (long)(n0 + ldr) * ldb + ldc0 * 8;

    auto aAddr = [&](int s, int r, int c) -> uint32_t {
        return sbase + s * STAGE_BYTES + ((((uint32_t)r << 3) | (uint32_t)(c ^ (r & 7))) << 4);
    };
    auto bAddr = [&](int s, int r, int c) -> uint32_t {
        return sbase + s * STAGE_BYTES + BM * BKE * 2 +
               ((((uint32_t)r << 3) | (uint32_t)(c ^ (r & 7))) << 4);
    };
    auto prefetch = [&](int s, int ch) {
        const bf16* ap = Ag + (long)ch * BKE;
        const bf16* bp = Bg + (long)ch * BKE;
        #pragma unroll
        for (int c = 0; c < 4; c++) {
            cp_async16(aAddr(s, ldr, ldc0 + c), ap + c * 8);
            cp_async16(bAddr(s, ldr, ldc0 + c), bp + c * 8);
        }
    };

    float acc[2][8][4] = {};
    const int NCH = Kp / BKE;

    prefetch(0, 0); CP_COMMIT();
    prefetch(1, 1); CP_COMMIT();

    // ldmatrix lane address components
    const int a_r  = lane & 15;
    const int a_kc = lane >> 4;
    const int b_r  = (lane & 7) + ((lane >> 4) << 3);
    const int b_kc = (lane >> 3) & 1;

    for (int ch = 0; ch < NCH; ch++) {
        CP_WAIT1();
        __syncthreads();
        if (ch + STAGES - 1 < NCH) prefetch((ch + 2) % STAGES, ch + 2);
        CP_COMMIT();
        const int s = ch % STAGES;
        #pragma unroll
        for (int ks = 0; ks < 4; ks++) {
            uint32_t a[2][4], b[4][4];
            #pragma unroll
            for (int mt = 0; mt < 2; mt++) {
                int r = wm * 32 + mt * 16 + a_r;
                ldm_x4(a[mt], aAddr(s, r, 2 * ks + a_kc));
            }
            #pragma unroll
            for (int g = 0; g < 4; g++) {
                int r = wn * 64 + g * 16 + b_r;
                ldm_x4(b[g], bAddr(s, r, 2 * ks + b_kc));
            }
            #pragma unroll
            for (int mt = 0; mt < 2; mt++)
                #pragma unroll
                for (int j = 0; j < 8; j++)
                    mma16816(acc[mt][j], a[mt], &b[j >> 1][(j & 1) * 2]);
        }
    }
    __syncthreads();

    // ---- bounce fragments to smem fp32 tile [128][132] ----
    float* S = reinterpret_cast<float*>(smem);
    #pragma unroll
    for (int mt = 0; mt < 2; mt++)
        #pragma unroll
        for (int j = 0; j < 8; j++) {
            int r  = wm * 32 + mt * 16 + (lane >> 2);
            int cc = wn * 64 + j * 8 + (lane & 3) * 2;
            S[r * 132 + cc]           = acc[mt][j][0];
            S[r * 132 + cc + 1]       = acc[mt][j][1];
            S[(r + 8) * 132 + cc]     = acc[mt][j][2];
            S[(r + 8) * 132 + cc + 1] = acc[mt][j][3];
        }
    __syncthreads();

    if (EPI == 0) {
        float* Cf = reinterpret_cast<float*>(Cout) + (long)z * sC;
        #pragma unroll
        for (int i = 0; i < 16; i++) {
            int idx = tid + i * 256;
            int r = idx >> 5, c4 = (idx & 31) * 4;
            float4 v;
            v.x = S[r * 132 + c4 + 0] * alpha;
            v.y = S[r * 132 + c4 + 1] * alpha;
            v.z = S[r * 132 + c4 + 2] * alpha;
            v.w = S[r * 132 + c4 + 3] * alpha;
            *reinterpret_cast<float4*>(Cf + (long)(m0 + r) * ldOut + n0 + c4) = v;
        }
    } else if (EPI == 1 || EPI == 2) {
        bf16* Cb = reinterpret_cast<bf16*>(Cout) + (long)z * sC;
        #pragma unroll
        for (int i = 0; i < 32; i++) {
            int idx = tid + i * 256;
            int r = idx >> 6, n = (idx & 63) * 2;
            float f0 = S[r * 132 + n] * alpha;
            float f1 = S[r * 132 + n + 1] * alpha;
            if (bias) { f0 += bias[n0 + n]; f1 += bias[n0 + n + 1]; }
            uint32_t h0, l0, h1, l1;
            split_bf(f0, h0, l0);
            split_bf(f1, h1, l1);
            uint32_t w0, w1, w2;
            if (EPI == 1) { w0 = h0 | (h0 << 16); w1 = l0 | (h1 << 16); w2 = h1 | (l1 << 16); }
            else          { w0 = h0 | (l0 << 16); w1 = h0 | (h1 << 16); w2 = l1 | (h1 << 16); }
            uint32_t* d = reinterpret_cast<uint32_t*>(Cb + (long)(m0 + r) * ldOut + 3 * (n0 + n));
            d[0] = w0; d[1] = w1; d[2] = w2;
        }
    } else {  // EPI 3: transposed expand, B-pattern
        bf16* Cb = reinterpret_cast<bf16*>(Cout) + (long)z * sC;
        const long colbase = (long)z * colPerZ + 3L * m0;
        #pragma unroll
        for (int i = 0; i < 32; i++) {
            int idx = tid + i * 256;
            int n = idx >> 6, mp = idx & 63;
            int m = mp * 2;
            float bb = bias ? bias[n0 + n] : 0.0f;
            float f0 = S[m * 132 + n] * alpha + bb;
            float f1 = S[(m + 1) * 132 + n] * alpha + bb;
            uint32_t h0, l0, h1, l1;
            split_bf(f0, h0, l0);
            split_bf(f1, h1, l1);
            uint32_t w0 = h0 | (l0 << 16);
            uint32_t w1 = h0 | (h1 << 16);
            uint32_t w2 = l1 | (h1 << 16);
            uint32_t* d = reinterpret_cast<uint32_t*>(Cb + (long)(n0 + n) * ldOut + colbase + 3 * m);
            d[0] = w0; d[1] = w1; d[2] = w2;
        }
    }
}

// ---------------- softmax (scale folded) + A-pattern expansion ----------------
__global__ __launch_bounds__(256)
void softmax_expand(const float* __restrict__ Sc, bf16* __restrict__ att)
{
    const int row = blockIdx.x;                    // 0..NH*NT-1
    const float* p = Sc + (size_t)row * NT;
    uint32_t* d = reinterpret_cast<uint32_t*>(att + (size_t)row * 3 * NT);
    const int tid = threadIdx.x;
    const float scale = rsqrtf((float)NT);
    __shared__ float red[256];

    float v[8];
    {
        float4 f0 = reinterpret_cast<const float4*>(p)[tid * 2];
        float4 f1 = reinterpret_cast<const float4*>(p)[tid * 2 + 1];
        v[0] = f0.x * scale; v[1] = f0.y * scale; v[2] = f0.z * scale; v[3] = f0.w * scale;
        v[4] = f1.x * scale; v[5] = f1.y * scale; v[6] = f1.z * scale; v[7] = f1.w * scale;
    }
    float mx = v[0];
    #pragma unroll
    for (int i = 1; i < 8; i++) mx = fmaxf(mx, v[i]);
    red[tid] = mx;
    __syncthreads();
    for (int s = 128; s > 0; s >>= 1) {
        if (tid < s) red[tid] = fmaxf(red[tid], red[tid + s]);
        __syncthreads();
    }
    mx = red[0];
    __syncthreads();

    float sum = 0.0f;
    #pragma unroll
    for (int i = 0; i < 8; i++) { v[i] = expf(v[i] - mx); sum += v[i]; }
    red[tid] = sum;
    __syncthreads();
    for (int s = 128; s > 0; s >>= 1) {
        if (tid < s) red[tid] += red[tid + s];
        __syncthreads();
    }
    const float inv = 1.0f / red[0];

    #pragma unroll
    for (int j = 0; j < 4; j++) {
        float f0 = v[2 * j] * inv;
        float f1 = v[2 * j + 1] * inv;
        uint32_t h0, l0, h1, l1;
        split_bf(f0, h0, l0);
        split_bf(f1, h1, l1);
        // A-pattern triples
        d[tid * 12 + 3 * j + 0] = h0 | (h0 << 16);
        d[tid * 12 + 3 * j + 1] = l0 | (h1 << 16);
        d[tid * 12 + 3 * j + 2] = h1 | (l1 << 16);
    }
}

// ---------------- split-K reduce + bias + residual + LayerNorm ----------------
__global__ __launch_bounds__(128)
void reduce_ln_kernel(const float* __restrict__ parts, const float* __restrict__ zres,
                      const float* __restrict__ bfv, float* __restrict__ out)
{
    const int row = blockIdx.x;
    const int tid = threadIdx.x;
    float4 acc = reinterpret_cast<const float4*>(zres + (size_t)row * NE)[tid];
    const float b = bfv[row];
    acc.x += b; acc.y += b; acc.z += b; acc.w += b;
    #pragma unroll
    for (int p = 0; p < SPLITK; p++) {
        float4 t = reinterpret_cast<const float4*>(
            parts + (size_t)p * NT * NE + (size_t)row * NE)[tid];
        acc.x += t.x; acc.y += t.y; acc.z += t.z; acc.w += t.w;
    }

    __shared__ float red[128];
    red[tid] = acc.x + acc.y + acc.z + acc.w;
    __syncthreads();
    for (int s = 64; s > 0; s >>= 1) {
        if (tid < s) red[tid] += red[tid + s];
        __syncthreads();
    }
    const float mean = red[0] * (1.0f / NE);
    __syncthreads();

    const float dx = acc.x - mean, dy = acc.y - mean, dz = acc.z - mean, dw = acc.w - mean;
    red[tid] = dx * dx + dy * dy + dz * dz + dw * dw;
    __syncthreads();
    for (int s = 64; s > 0; s >>= 1) {
        if (tid < s) red[tid] += red[tid + s];
        __syncthreads();
    }
    const float rstd = rsqrtf(red[0] * (1.0f / NE) + 1e-4f);

    float4 o;
    o.x = dx * rstd; o.y = dy * rstd; o.z = dz * rstd; o.w = dw * rstd;
    reinterpret_cast<float4*>(out + (size_t)row * NE)[tid] = o;
}

// ---------------- launch ----------------
static inline int eblocks(long npairs) {
    long b = (npairs + 1023) / 1024;
    if (b > 4096) b = 4096;
    if (b < 1) b = 1;
    return (int)b;
}

extern "C" void kernel_launch(void* const* d_in, const int* in_sizes, int n_in,
                              void* d_out, int out_size)
{
    const float* x  = (const float*)d_in[0];
    const float* y  = (const float*)d_in[1];
    const float* z  = (const float*)d_in[2];
    const float* Wq = (const float*)d_in[3];
    const float* bq = (const float*)d_in[4];
    const float* Wk = (const float*)d_in[5];
    const float* bk = (const float*)d_in[6];
    const float* Wv = (const float*)d_in[7];
    const float* bv = (const float*)d_in[8];
    const float* Wf = (const float*)d_in[9];
    const float* bf = (const float*)d_in[10];
    float* out = (float*)d_out;

    bf16 *xe, *ye, *ze, *Wqe, *Wke, *Wve, *Wfe, *q, *k, *v, *att, *hd;
    float *sc, *pt;
    cudaGetSymbolAddress((void**)&xe,  g_xe);
    cudaGetSymbolAddress((void**)&ye,  g_ye);
    cudaGetSymbolAddress((void**)&ze,  g_ze);
    cudaGetSymbolAddress((void**)&Wqe, g_Wqe);
    cudaGetSymbolAddress((void**)&Wke, g_Wke);
    cudaGetSymbolAddress((void**)&Wve, g_Wve);
    cudaGetSymbolAddress((void**)&Wfe, g_Wfe);
    cudaGetSymbolAddress((void**)&q,   g_q);
    cudaGetSymbolAddress((void**)&k,   g_k);
    cudaGetSymbolAddress((void**)&v,   g_v);
    cudaGetSymbolAddress((void**)&att, g_att);
    cudaGetSymbolAddress((void**)&hd,  g_hd);
    cudaGetSymbolAddress((void**)&sc,  g_sc);
    cudaGetSymbolAddress((void**)&pt,  g_part);

    cudaFuncSetAttribute(mma_gemm<0>, cudaFuncAttributeMaxDynamicSharedMemorySize, GEMM_SMEM);
    cudaFuncSetAttribute(mma_gemm<1>, cudaFuncAttributeMaxDynamicSharedMemorySize, GEMM_SMEM);
    cudaFuncSetAttribute(mma_gemm<2>, cudaFuncAttributeMaxDynamicSharedMemorySize, GEMM_SMEM);
    cudaFuncSetAttribute(mma_gemm<3>, cudaFuncAttributeMaxDynamicSharedMemorySize, GEMM_SMEM);

    // ---- expand inputs ----
    const long pXE = (long)NT * NE / 2;
    const long pW  = (long)NH * NE * NE / 2;
    const long pWF = (long)NT * NHT / 2;
    expand_kernel<0><<<eblocks(pXE), 256>>>(x, xe, pXE);
    expand_kernel<0><<<eblocks(pXE), 256>>>(y, ye, pXE);
    expand_kernel<0><<<eblocks(pXE), 256>>>(z, ze, pXE);
    expand_kernel<1><<<eblocks(pW), 256>>>(Wq, Wqe, pW);
    expand_kernel<1><<<eblocks(pW), 256>>>(Wk, Wke, pW);
    expand_kernel<1><<<eblocks(pW), 256>>>(Wv, Wve, pW);
    expand_kernel<0><<<eblocks(pWF), 256>>>(Wf, Wfe, pWF);

    const long L3E  = 3L * NE;     // 1536
    const long L3T  = 3L * NT;     // 6144
    const long L3HT = 3L * NHT;    // 49152

    // ---- QKV projections (batched over heads) ----
    dim3 gP(NE / BN, NT / BM, NH);
    mma_gemm<1><<<gP, 256, GEMM_SMEM>>>(xe, Wqe, q, (int)L3E, L3E, L3E, L3E,
                                        0, (long)NE * L3E, (long)NT * L3E, 0,
                                        1.0f, bq, NE);
    mma_gemm<2><<<gP, 256, GEMM_SMEM>>>(ye, Wke, k, (int)L3E, L3E, L3E, L3E,
                                        0, (long)NE * L3E, (long)NT * L3E, 0,
                                        1.0f, bk, NE);
    mma_gemm<3><<<gP, 256, GEMM_SMEM>>>(ze, Wve, v, (int)L3E, L3E, L3E, L3T,
                                        0, (long)NE * L3E, (long)NE * L3T, 0,
                                        1.0f, bv, NE);

    // ---- scores (fp32, scale folded into softmax) ----
    dim3 gS(NT / BN, NT / BM, NH);
    mma_gemm<0><<<gS, 256, GEMM_SMEM>>>(q, k, sc, (int)L3E, L3E, L3E, NT,
                                        (long)NT * L3E, (long)NT * L3E, (long)NT * NT, 0,
                                        1.0f, nullptr, 0);

    // ---- softmax + expand ----
    softmax_expand<<<NH * NT, 256>>>(sc, att);

    // ---- heads = att @ v  -> transposed-expanded concat [E, 3HT] ----
    dim3 gAV(NE / BN, NT / BM, NH);
    mma_gemm<3><<<gAV, 256, GEMM_SMEM>>>(att, v, hd, (int)L3T, L3T, L3T, L3HT,
                                         (long)NT * L3T, (long)NE * L3T, 0, L3T,
                                         1.0f, nullptr, 0);

    // ---- final linear, split-K = 8 ----
    dim3 gF(NE / BN, NT / BM, SPLITK);
    mma_gemm<0><<<gF, 256, GEMM_SMEM>>>(Wfe, hd, pt, (int)(L3HT / SPLITK), L3HT, L3HT, NE,
                                        L3HT / SPLITK, L3HT / SPLITK, (long)NT * NE, 0,
                                        1.0f, nullptr, 0);

    // ---- reduce + bias + residual + LayerNorm ----
    reduce_ln_kernel<<<NT, 128>>>(pt, z, bf, out);
}

// round 6
// speedup vs baseline: 4.3620x; 1.5446x over previous
#include <cuda_runtime.h>
#include <cuda_fp16.h>
#include <math.h>
#include <stdint.h>

#define NH 8
#define NT 2048
#define NE 512
#define NHT (NH * NT)
#define SPLITK 8

typedef __half fp16;

// ---------------- scratch (device globals; no allocation anywhere) ----------------
// K-expansion x2 along the contraction dim. One fp32 element -> one uint32 word
// (two fp16). A-pattern word = (hi | lo<<16); B-pattern word = (hi | hi<<16).
__device__ __align__(256) fp16 g_xe[(size_t)NT * 2 * NE];
__device__ __align__(256) fp16 g_ye[(size_t)NT * 2 * NE];
__device__ __align__(256) fp16 g_ze[(size_t)NT * 2 * NE];
__device__ __align__(256) fp16 g_Wqe[(size_t)NH * NE * 2 * NE];
__device__ __align__(256) fp16 g_Wke[(size_t)NH * NE * 2 * NE];
__device__ __align__(256) fp16 g_Wve[(size_t)NH * NE * 2 * NE];
__device__ __align__(256) fp16 g_Wfe[(size_t)NT * 2 * NHT];
__device__ __align__(256) fp16 g_q[(size_t)NH * NT * 2 * NE];   // A-pattern rows [T,2E]
__device__ __align__(256) fp16 g_k[(size_t)NH * NT * 2 * NE];   // B-pattern rows [T,2E]
__device__ __align__(256) fp16 g_v[(size_t)NH * NE * 2 * NT];   // B-pattern transposed [E,2T]
__device__ __align__(256) float g_sc[(size_t)NH * NT * NT];     // fp32 scores
__device__ __align__(256) fp16 g_att[(size_t)NH * NT * 2 * NT]; // A-pattern [T,2T]
__device__ __align__(256) fp16 g_hd[(size_t)NE * 2 * NHT];      // B-pattern transposed [E,2HT]
__device__ __align__(256) float g_part[(size_t)SPLITK * NT * NE];

// ---------------- small helpers ----------------
__device__ __forceinline__ uint32_t smem_u32(const void* p) {
    uint32_t a;
    asm("{ .reg .u64 t; cvta.to.shared.u64 t, %1; cvt.u32.u64 %0, t; }" : "=r"(a) : "l"(p));
    return a;
}

__device__ __forceinline__ void cp_async16(uint32_t dst, const void* src) {
    asm volatile("cp.async.cg.shared.global [%0], [%1], 16;" :: "r"(dst), "l"(src));
}
#define CP_COMMIT() asm volatile("cp.async.commit_group;")
#define CP_WAIT1()  asm volatile("cp.async.wait_group 1;")

__device__ __forceinline__ void ldm_x4(uint32_t* r, uint32_t addr) {
    asm volatile("ldmatrix.sync.aligned.m8n8.x4.shared.b16 {%0,%1,%2,%3}, [%4];"
                 : "=r"(r[0]), "=r"(r[1]), "=r"(r[2]), "=r"(r[3]) : "r"(addr));
}

__device__ __forceinline__ void mma16816(float* c, const uint32_t* a, const uint32_t* b) {
    asm volatile(
        "mma.sync.aligned.m16n8k16.row.col.f32.f16.f16.f32 "
        "{%0,%1,%2,%3}, {%4,%5,%6,%7}, {%8,%9}, {%0,%1,%2,%3};"
        : "+f"(c[0]), "+f"(c[1]), "+f"(c[2]), "+f"(c[3])
        : "r"(a[0]), "r"(a[1]), "r"(a[2]), "r"(a[3]), "r"(b[0]), "r"(b[1]));
}

// split f into fp16 hi + lo
__device__ __forceinline__ void split_h(float f, uint32_t& h, uint32_t& l) {
    __half hb = __float2half_rn(f);
    float hf = __half2float(hb);
    __half lb = __float2half_rn(f - hf);
    h = (uint32_t)__half_as_ushort(hb);
    l = (uint32_t)__half_as_ushort(lb);
}
__device__ __forceinline__ uint32_t wordA(float f) {
    uint32_t h, l; split_h(f, h, l); return h | (l << 16);
}
__device__ __forceinline__ uint32_t wordB(float f) {
    __half hb = __float2half_rn(f);
    uint32_t h = (uint32_t)__half_as_ushort(hb);
    return h | (h << 16);
}

// ---------------- input expansion (elementwise fp32 -> uint32 word) ----------------
template <int PAT>   // 0 = A-pattern (hi,lo), 1 = B-pattern (hi,hi)
__global__ __launch_bounds__(256)
void expand_kernel(const float* __restrict__ src, fp16* __restrict__ dst, long n)
{
    long i = (long)blockIdx.x * blockDim.x + threadIdx.x;
    const long stride = (long)gridDim.x * blockDim.x;
    uint32_t* d32 = reinterpret_cast<uint32_t*>(dst);
    for (; i < n; i += stride) {
        float f = src[i];
        d32[i] = (PAT == 0) ? wordA(f) : wordB(f);
    }
}

// ---------------- mma.sync GEMM ----------------
// C[M=by*128, N=bx*128] = sum_k' A[m,k'] * B[n,k']   (TN, both row-major, K'-contig)
// EPI 0: fp32 out (alpha)
// EPI 1: A-pattern words in-row (+bias_n)       d[(m0+r)*ldW + n0+n]
// EPI 2: B-pattern words in-row (+bias_n)
// EPI 3: B-pattern words transposed (+bias_n)   d[(n0+n)*ldW + z*colPerZ + m0+m]
#define BM 128
#define BN 128
#define BKE 64
#define STAGES 3
#define STAGE_BYTES (BM * BKE * 2 + BN * BKE * 2)   // 32768
#define GEMM_SMEM (STAGES * STAGE_BYTES)            // 98304

template <int EPI>
__global__ __launch_bounds__(256, 2)
void mma_gemm(const fp16* __restrict__ A, const fp16* __restrict__ B, void* Cout,
              int Kp, long lda, long ldb, long ldW,
              long sA, long sB, long sC, long colPerZ,
              float alpha, const float* __restrict__ bias, long sBias)
{
    extern __shared__ char smem[];
    const int tid = threadIdx.x, lane = tid & 31, wid = tid >> 5;
    const int wm = wid & 3, wn = wid >> 2;
    const int m0 = blockIdx.y * BM, n0 = blockIdx.x * BN, z = blockIdx.z;
    A += (long)z * sA;
    B += (long)z * sB;
    if (bias) bias += (long)z * sBias;
    const uint32_t sbase = smem_u32(smem);

    const int ldr  = tid >> 1;          // tile row 0..127
    const int ldc0 = (tid & 1) * 4;     // first 16B chunk
    const fp16* Ag = A + (long)(m0 + ldr) * lda + ldc0 * 8;
    const fp16* Bg = B + (long)(n0 + ldr) * ldb + ldc0 * 8;

    auto aAddr = [&](int s, int r, int c) -> uint32_t {
        return sbase + s * STAGE_BYTES + ((((uint32_t)r << 3) | (uint32_t)(c ^ (r & 7))) << 4);
    };
    auto bAddr = [&](int s, int r, int c) -> uint32_t {
        return sbase + s * STAGE_BYTES + BM * BKE * 2 +
               ((((uint32_t)r << 3) | (uint32_t)(c ^ (r & 7))) << 4);
    };
    auto prefetch = [&](int s, int ch) {
        const fp16* ap = Ag + (long)ch * BKE;
        const fp16* bp = Bg + (long)ch * BKE;
        #pragma unroll
        for (int c = 0; c < 4; c++) {
            cp_async16(aAddr(s, ldr, ldc0 + c), ap + c * 8);
            cp_async16(bAddr(s, ldr, ldc0 + c), bp + c * 8);
        }
    };

    float acc[2][8][4] = {};
    const int NCH = Kp / BKE;

    prefetch(0, 0); CP_COMMIT();
    prefetch(1, 1); CP_COMMIT();

    const int a_r  = lane & 15;
    const int a_kc = lane >> 4;
    const int b_r  = (lane & 7) + ((lane >> 4) << 3);
    const int b_kc = (lane >> 3) & 1;

    for (int ch = 0; ch < NCH; ch++) {
        CP_WAIT1();
        __syncthreads();
        if (ch + 2 < NCH) prefetch((ch + 2) % STAGES, ch + 2);
        CP_COMMIT();
        const int s = ch % STAGES;
        #pragma unroll
        for (int ks = 0; ks < 4; ks++) {
            uint32_t a[2][4], b[4][4];
            #pragma unroll
            for (int mt = 0; mt < 2; mt++) {
                int r = wm * 32 + mt * 16 + a_r;
                ldm_x4(a[mt], aAddr(s, r, 2 * ks + a_kc));
            }
            #pragma unroll
            for (int g = 0; g < 4; g++) {
                int r = wn * 64 + g * 16 + b_r;
                ldm_x4(b[g], bAddr(s, r, 2 * ks + b_kc));
            }
            #pragma unroll
            for (int mt = 0; mt < 2; mt++)
                #pragma unroll
                for (int j = 0; j < 8; j++)
                    mma16816(acc[mt][j], a[mt], &b[j >> 1][(j & 1) * 2]);
        }
    }
    __syncthreads();

    // ---- bounce fragments to smem fp32 tile [128][132] ----
    float* S = reinterpret_cast<float*>(smem);
    #pragma unroll
    for (int mt = 0; mt < 2; mt++)
        #pragma unroll
        for (int j = 0; j < 8; j++) {
            int r  = wm * 32 + mt * 16 + (lane >> 2);
            int cc = wn * 64 + j * 8 + (lane & 3) * 2;
            S[r * 132 + cc]           = acc[mt][j][0];
            S[r * 132 + cc + 1]       = acc[mt][j][1];
            S[(r + 8) * 132 + cc]     = acc[mt][j][2];
            S[(r + 8) * 132 + cc + 1] = acc[mt][j][3];
        }
    __syncthreads();

    if (EPI == 0) {
        float* Cf = reinterpret_cast<float*>(Cout) + (long)z * sC;
        #pragma unroll
        for (int i = 0; i < 16; i++) {
            int idx = tid + i * 256;
            int r = idx >> 5, c4 = (idx & 31) * 4;
            float4 v;
            v.x = S[r * 132 + c4 + 0] * alpha;
            v.y = S[r * 132 + c4 + 1] * alpha;
            v.z = S[r * 132 + c4 + 2] * alpha;
            v.w = S[r * 132 + c4 + 3] * alpha;
            *reinterpret_cast<float4*>(Cf + (long)(m0 + r) * ldW + n0 + c4) = v;
        }
    } else if (EPI == 1 || EPI == 2) {
        uint32_t* Cw = reinterpret_cast<uint32_t*>(Cout) + (long)z * sC;
        #pragma unroll
        for (int i = 0; i < 16; i++) {
            int idx = tid + i * 256;
            int r = idx >> 5, c4 = (idx & 31) * 4;
            uint4 w;
            float f0 = S[r * 132 + c4 + 0] * alpha;
            float f1 = S[r * 132 + c4 + 1] * alpha;
            float f2 = S[r * 132 + c4 + 2] * alpha;
            float f3 = S[r * 132 + c4 + 3] * alpha;
            if (bias) {
                f0 += bias[n0 + c4 + 0];
                f1 += bias[n0 + c4 + 1];
                f2 += bias[n0 + c4 + 2];
                f3 += bias[n0 + c4 + 3];
            }
            if (EPI == 1) { w.x = wordA(f0); w.y = wordA(f1); w.z = wordA(f2); w.w = wordA(f3); }
            else          { w.x = wordB(f0); w.y = wordB(f1); w.z = wordB(f2); w.w = wordB(f3); }
            *reinterpret_cast<uint4*>(Cw + (long)(m0 + r) * ldW + n0 + c4) = w;
        }
    } else {  // EPI 3: transposed, B-pattern words
        uint32_t* Cw = reinterpret_cast<uint32_t*>(Cout) + (long)z * sC;
        const long colbase = (long)z * colPerZ + m0;
        #pragma unroll
        for (int i = 0; i < 32; i++) {
            int idx = tid + i * 256;
            int n = idx >> 6, m = (idx & 63) * 2;
            float bb = bias ? bias[n0 + n] : 0.0f;
            uint2 w;
            w.x = wordB(S[m * 132 + n] * alpha + bb);
            w.y = wordB(S[(m + 1) * 132 + n] * alpha + bb);
            *reinterpret_cast<uint2*>(Cw + (long)(n0 + n) * ldW + colbase + m) = w;
        }
    }
}

// ---------------- softmax (scale folded) + A-pattern expansion ----------------
__global__ __launch_bounds__(256)
void softmax_expand(const float* __restrict__ Sc, fp16* __restrict__ att)
{
    const int row = blockIdx.x;                    // 0..NH*NT-1
    const float* p = Sc + (size_t)row * NT;
    uint32_t* d = reinterpret_cast<uint32_t*>(att) + (size_t)row * NT;
    const int tid = threadIdx.x;
    const float scale = rsqrtf((float)NT);
    __shared__ float red[256];

    float v[8];
    {
        float4 f0 = reinterpret_cast<const float4*>(p)[tid * 2];
        float4 f1 = reinterpret_cast<const float4*>(p)[tid * 2 + 1];
        v[0] = f0.x * scale; v[1] = f0.y * scale; v[2] = f0.z * scale; v[3] = f0.w * scale;
        v[4] = f1.x * scale; v[5] = f1.y * scale; v[6] = f1.z * scale; v[7] = f1.w * scale;
    }
    float mx = v[0];
    #pragma unroll
    for (int i = 1; i < 8; i++) mx = fmaxf(mx, v[i]);
    red[tid] = mx;
    __syncthreads();
    for (int s = 128; s > 0; s >>= 1) {
        if (tid < s) red[tid] = fmaxf(red[tid], red[tid + s]);
        __syncthreads();
    }
    mx = red[0];
    __syncthreads();

    float sum = 0.0f;
    #pragma unroll
    for (int i = 0; i < 8; i++) { v[i] = expf(v[i] - mx); sum += v[i]; }
    red[tid] = sum;
    __syncthreads();
    for (int s = 128; s > 0; s >>= 1) {
        if (tid < s) red[tid] += red[tid + s];
        __syncthreads();
    }
    const float inv = 1.0f / red[0];

    uint2 w[4];
    #pragma unroll
    for (int j = 0; j < 4; j++) {
        w[j].x = wordA(v[2 * j] * inv);
        w[j].y = wordA(v[2 * j + 1] * inv);
    }
    #pragma unroll
    for (int j = 0; j < 4; j++)
        reinterpret_cast<uint2*>(d + tid * 8)[j] = w[j];
}

// ---------------- split-K reduce + bias + residual + LayerNorm ----------------
__global__ __launch_bounds__(128)
void reduce_ln_kernel(const float* __restrict__ parts, const float* __restrict__ zres,
                      const float* __restrict__ bfv, float* __restrict__ out)
{
    const int row = blockIdx.x;
    const int tid = threadIdx.x;
    float4 acc = reinterpret_cast<const float4*>(zres + (size_t)row * NE)[tid];
    const float b = bfv[row];
    acc.x += b; acc.y += b; acc.z += b; acc.w += b;
    #pragma unroll
    for (int p = 0; p < SPLITK; p++) {
        float4 t = reinterpret_cast<const float4*>(
            parts + (size_t)p * NT * NE + (size_t)row * NE)[tid];
        acc.x += t.x; acc.y += t.y; acc.z += t.z; acc.w += t.w;
    }

    __shared__ float red[128];
    red[tid] = acc.x + acc.y + acc.z + acc.w;
    __syncthreads();
    for (int s = 64; s > 0; s >>= 1) {
        if (tid < s) red[tid] += red[tid + s];
        __syncthreads();
    }
    const float mean = red[0] * (1.0f / NE);
    __syncthreads();

    const float dx = acc.x - mean, dy = acc.y - mean, dz = acc.z - mean, dw = acc.w - mean;
    red[tid] = dx * dx + dy * dy + dz * dz + dw * dw;
    __syncthreads();
    for (int s = 64; s > 0; s >>= 1) {
        if (tid < s) red[tid] += red[tid + s];
        __syncthreads();
    }
    const float rstd = rsqrtf(red[0] * (1.0f / NE) + 1e-4f);

    float4 o;
    o.x = dx * rstd; o.y = dy * rstd; o.z = dz * rstd; o.w = dw * rstd;
    reinterpret_cast<float4*>(out + (size_t)row * NE)[tid] = o;
}

// ---------------- launch ----------------
static inline int eblocks(long n) {
    long b = (n + 2047) / 2048;
    if (b > 4096) b = 4096;
    if (b < 1) b = 1;
    return (int)b;
}

extern "C" void kernel_launch(void* const* d_in, const int* in_sizes, int n_in,
                              void* d_out, int out_size)
{
    const float* x  = (const float*)d_in[0];
    const float* y  = (const float*)d_in[1];
    const float* z  = (const float*)d_in[2];
    const float* Wq = (const float*)d_in[3];
    const float* bq = (const float*)d_in[4];
    const float* Wk = (const float*)d_in[5];
    const float* bk = (const float*)d_in[6];
    const float* Wv = (const float*)d_in[7];
    const float* bv = (const float*)d_in[8];
    const float* Wf = (const float*)d_in[9];
    const float* bf = (const float*)d_in[10];
    float* out = (float*)d_out;

    fp16 *xe, *ye, *ze, *Wqe, *Wke, *Wve, *Wfe, *q, *k, *v, *att, *hd;
    float *sc, *pt;
    cudaGetSymbolAddress((void**)&xe,  g_xe);
    cudaGetSymbolAddress((void**)&ye,  g_ye);
    cudaGetSymbolAddress((void**)&ze,  g_ze);
    cudaGetSymbolAddress((void**)&Wqe, g_Wqe);
    cudaGetSymbolAddress((void**)&Wke, g_Wke);
    cudaGetSymbolAddress((void**)&Wve, g_Wve);
    cudaGetSymbolAddress((void**)&Wfe, g_Wfe);
    cudaGetSymbolAddress((void**)&q,   g_q);
    cudaGetSymbolAddress((void**)&k,   g_k);
    cudaGetSymbolAddress((void**)&v,   g_v);
    cudaGetSymbolAddress((void**)&att, g_att);
    cudaGetSymbolAddress((void**)&hd,  g_hd);
    cudaGetSymbolAddress((void**)&sc,  g_sc);
    cudaGetSymbolAddress((void**)&pt,  g_part);

    cudaFuncSetAttribute(mma_gemm<0>, cudaFuncAttributeMaxDynamicSharedMemorySize, GEMM_SMEM);
    cudaFuncSetAttribute(mma_gemm<1>, cudaFuncAttributeMaxDynamicSharedMemorySize, GEMM_SMEM);
    cudaFuncSetAttribute(mma_gemm<2>, cudaFuncAttributeMaxDynamicSharedMemorySize, GEMM_SMEM);
    cudaFuncSetAttribute(mma_gemm<3>, cudaFuncAttributeMaxDynamicSharedMemorySize, GEMM_SMEM);

    // ---- expand inputs ----
    const long nXE = (long)NT * NE;
    const long nW  = (long)NH * NE * NE;
    const long nWF = (long)NT * NHT;
    expand_kernel<0><<<eblocks(nXE), 256>>>(x, xe, nXE);
    expand_kernel<0><<<eblocks(nXE), 256>>>(y, ye, nXE);
    expand_kernel<0><<<eblocks(nXE), 256>>>(z, ze, nXE);
    expand_kernel<1><<<eblocks(nW), 256>>>(Wq, Wqe, nW);
    expand_kernel<1><<<eblocks(nW), 256>>>(Wk, Wke, nW);
    expand_kernel<1><<<eblocks(nW), 256>>>(Wv, Wve, nW);
    expand_kernel<0><<<eblocks(nWF), 256>>>(Wf, Wfe, nWF);

    const long L2E  = 2L * NE;     // 1024 fp16
    const long L2T  = 2L * NT;     // 4096 fp16
    const long L2HT = 2L * NHT;    // 32768 fp16

    // ---- QKV projections (batched over heads) ----
    dim3 gP(NE / BN, NT / BM, NH);
    // q: A-pattern rows [T, 2E]
    mma_gemm<1><<<gP, 256, GEMM_SMEM>>>(xe, Wqe, q, (int)L2E, L2E, L2E, NE,
                                        0, (long)NE * L2E, (long)NT * NE, 0,
                                        1.0f, bq, NE);
    // k: B-pattern rows [T, 2E]
    mma_gemm<2><<<gP, 256, GEMM_SMEM>>>(ye, Wke, k, (int)L2E, L2E, L2E, NE,
                                        0, (long)NE * L2E, (long)NT * NE, 0,
                                        1.0f, bk, NE);
    // v: B-pattern transposed [E, 2T] per head
    mma_gemm<3><<<gP, 256, GEMM_SMEM>>>(ze, Wve, v, (int)L2E, L2E, L2E, NT,
                                        0, (long)NE * L2E, (long)NE * NT, 0,
                                        1.0f, bv, NE);

    // ---- scores (fp32, 1/sqrt(T) folded into softmax) ----
    dim3 gS(NT / BN, NT / BM, NH);
    mma_gemm<0><<<gS, 256, GEMM_SMEM>>>(q, k, sc, (int)L2E, L2E, L2E, NT,
                                        (long)NT * L2E, (long)NT * L2E, (long)NT * NT, 0,
                                        1.0f, nullptr, 0);

    // ---- softmax + A-pattern expand ----
    softmax_expand<<<NH * NT, 256>>>(sc, att);

    // ---- heads = att @ v  -> B-pattern transposed concat [E, 2HT] ----
    dim3 gAV(NE / BN, NT / BM, NH);
    mma_gemm<3><<<gAV, 256, GEMM_SMEM>>>(att, v, hd, (int)L2T, L2T, L2T, NHT,
                                         (long)NT * L2T, (long)NE * L2T, 0, NT,
                                         1.0f, nullptr, 0);

    // ---- final linear, split-K = 8 ----
    dim3 gF(NE / BN, NT / BM, SPLITK);
    mma_gemm<0><<<gF, 256, GEMM_SMEM>>>(Wfe, hd, pt, (int)(L2HT / SPLITK), L2HT, L2HT, NE,
                                        L2HT / SPLITK, L2HT / SPLITK, (long)NT * NE, 0,
                                        1.0f, nullptr, 0);

    // ---- reduce + bias + residual + LayerNorm ----
    reduce_ln_kernel<<<NT, 128>>>(pt, z, bf, out);
}